// round 1
// baseline (speedup 1.0000x reference)
#include <cuda_runtime.h>
#include <math.h>
#include <stdint.h>

// Problem constants
#define BB   2
#define TT   2048
#define CC   1024
#define HH   16
#define HD   64
#define MROWS (BB*TT)        // 4096
#define N_QKV (3*CC)         // 3072

// ---------------------------------------------------------------------------
// Scratch (device globals — no allocations allowed)
// ---------------------------------------------------------------------------
__device__ float g_q[BB*HH*TT*HD];   // [B,H,T,HD]
__device__ float g_k[BB*HH*TT*HD];
__device__ float g_v[BB*HH*TT*HD];
__device__ float g_y[MROWS*CC];      // attention output in [B,T,C]

// ---------------------------------------------------------------------------
// SGEMM: C[M,N] = A[M,K] @ B[K,N] (+bias). 128x128x8 tiling, 8x8 per thread.
// MODE 0: epilogue scatters into g_q/g_k/g_v ([B,H,T,HD]) with bias.
// MODE 1: epilogue writes C = acc + bias (row-major [M,N]).
// ---------------------------------------------------------------------------
template <int MODE>
__global__ __launch_bounds__(256)
void sgemm_kernel(const float* __restrict__ A, const float* __restrict__ B,
                  const float* __restrict__ bias, float* __restrict__ C,
                  int M, int N, int K)
{
    __shared__ float As[8][128];
    __shared__ float Bs[8][128];

    const int tid  = threadIdx.x;
    const int cRow = blockIdx.y;
    const int cCol = blockIdx.x;

    const int aRow = tid >> 1;            // 0..127
    const int aCol = (tid & 1) << 2;      // 0 or 4
    const int bRow = tid >> 5;            // 0..7
    const int bCol = (tid & 31) << 2;     // 0..124

    const int tRow = tid >> 4;            // 0..15
    const int tCol = tid & 15;            // 0..15

    const float* Ag = A + (size_t)cRow * 128 * K;
    const float* Bg = B + (size_t)cCol * 128;

    float acc[8][8];
#pragma unroll
    for (int i = 0; i < 8; i++)
#pragma unroll
        for (int j = 0; j < 8; j++) acc[i][j] = 0.0f;

    for (int k0 = 0; k0 < K; k0 += 8) {
        float4 av = *(const float4*)(Ag + (size_t)aRow * K + k0 + aCol);
        As[aCol + 0][aRow] = av.x;
        As[aCol + 1][aRow] = av.y;
        As[aCol + 2][aRow] = av.z;
        As[aCol + 3][aRow] = av.w;
        float4 bv = *(const float4*)(Bg + (size_t)(k0 + bRow) * N + bCol);
        *(float4*)&Bs[bRow][bCol] = bv;
        __syncthreads();

#pragma unroll
        for (int k = 0; k < 8; k++) {
            float rM[8], rN[8];
            *(float4*)&rM[0] = *(const float4*)&As[k][tRow * 8];
            *(float4*)&rM[4] = *(const float4*)&As[k][tRow * 8 + 4];
            *(float4*)&rN[0] = *(const float4*)&Bs[k][tCol * 8];
            *(float4*)&rN[4] = *(const float4*)&Bs[k][tCol * 8 + 4];
#pragma unroll
            for (int i = 0; i < 8; i++)
#pragma unroll
                for (int j = 0; j < 8; j++)
                    acc[i][j] = fmaf(rM[i], rN[j], acc[i][j]);
        }
        __syncthreads();
    }

    const int m0 = cRow * 128 + tRow * 8;
    const int n0 = cCol * 128 + tCol * 8;

    float bb[8];
    *(float4*)&bb[0] = *(const float4*)(bias + n0);
    *(float4*)&bb[4] = *(const float4*)(bias + n0 + 4);

    if (MODE == 0) {
        // n0 is 8-aligned so the 8 columns stay within one section and one head
        const int sec = n0 >> 10;         // 0=q 1=k 2=v
        const int c0  = n0 & 1023;
        const int h   = c0 >> 6;
        const int d0  = c0 & 63;
        float* dst = (sec == 0) ? g_q : ((sec == 1) ? g_k : g_v);
#pragma unroll
        for (int i = 0; i < 8; i++) {
            int m = m0 + i;
            int b = m >> 11;              // /2048
            int t = m & 2047;
            float* p = dst + (((size_t)(b * HH + h) * TT + t) * HD + d0);
            float4 v0 = make_float4(acc[i][0] + bb[0], acc[i][1] + bb[1],
                                    acc[i][2] + bb[2], acc[i][3] + bb[3]);
            float4 v1 = make_float4(acc[i][4] + bb[4], acc[i][5] + bb[5],
                                    acc[i][6] + bb[6], acc[i][7] + bb[7]);
            *(float4*)p       = v0;
            *(float4*)(p + 4) = v1;
        }
    } else {
#pragma unroll
        for (int i = 0; i < 8; i++) {
            float* p = C + (size_t)(m0 + i) * N + n0;
            float4 v0 = make_float4(acc[i][0] + bb[0], acc[i][1] + bb[1],
                                    acc[i][2] + bb[2], acc[i][3] + bb[3]);
            float4 v1 = make_float4(acc[i][4] + bb[4], acc[i][5] + bb[5],
                                    acc[i][6] + bb[6], acc[i][7] + bb[7]);
            *(float4*)p       = v0;
            *(float4*)(p + 4) = v1;
        }
    }
}

// ---------------------------------------------------------------------------
// Flash attention (fp32): one block = 128 q rows of one (b,h).
// 256 threads; per thread 8 q-rows x 4 k-cols of S, 8 q-rows x 4 d-cols of O.
// K tile = 64. Causal: process tiles 0 .. 2*bx+1 only, mask on the diagonal.
// SMEM (dynamic): Qs[64][128] d-major | Ks[64][68] d-major | Vs[64][64] | Ps[64][128]
// ---------------------------------------------------------------------------
#define ATTN_SMEM_FLOATS (64*128 + 64*68 + 64*64 + 64*128)
#define ATTN_SMEM_BYTES  (ATTN_SMEM_FLOATS * 4)

__global__ __launch_bounds__(256)
void attn_kernel(float* __restrict__ Yg)
{
    extern __shared__ float sm[];
    float* Qs = sm;                   // [d][q]  stride 128
    float* Ks = Qs + 64 * 128;        // [d][t]  stride 68
    float* Vs = Ks + 64 * 68;         // [t][d]  stride 64
    float* Ps = Vs + 64 * 64;         // [k][q]  stride 128

    const int tid   = threadIdx.x;
    const int bh    = blockIdx.y;                 // 0..31
    const int qbase = blockIdx.x * 128;
    const float scale = 0.125f;                   // 1/sqrt(64)

    const float* Qp = g_q + (size_t)bh * TT * HD;
    const float* Kp = g_k + (size_t)bh * TT * HD;
    const float* Vp = g_v + (size_t)bh * TT * HD;

    // Load Q tile transposed (d-major)
    for (int idx = tid; idx < 128 * 16; idx += 256) {
        int t  = idx >> 4;
        int dq = idx & 15;
        float4 v = *(const float4*)(Qp + (size_t)(qbase + t) * HD + dq * 4);
        int d = dq * 4;
        Qs[(d + 0) * 128 + t] = v.x;
        Qs[(d + 1) * 128 + t] = v.y;
        Qs[(d + 2) * 128 + t] = v.z;
        Qs[(d + 3) * 128 + t] = v.w;
    }

    const int tRow = tid >> 4;   // 0..15 (q group)
    const int tCol = tid & 15;   // 0..15 (k / d group)

    float O[8][4];
    float mrow[8], lrow[8];
#pragma unroll
    for (int i = 0; i < 8; i++) {
        mrow[i] = -1e30f;
        lrow[i] = 0.0f;
#pragma unroll
        for (int j = 0; j < 4; j++) O[i][j] = 0.0f;
    }

    const int ntiles = 2 * blockIdx.x + 2;
    for (int kt = 0; kt < ntiles; kt++) {
        const int kbase = kt * 64;
        __syncthreads();   // prior PV gemm done with Ks/Vs/Ps
        // Load K transposed + V natural
        for (int idx = tid; idx < 64 * 16; idx += 256) {
            int t  = idx >> 4;
            int dq = idx & 15;
            float4 kv = *(const float4*)(Kp + (size_t)(kbase + t) * HD + dq * 4);
            int d = dq * 4;
            Ks[(d + 0) * 68 + t] = kv.x;
            Ks[(d + 1) * 68 + t] = kv.y;
            Ks[(d + 2) * 68 + t] = kv.z;
            Ks[(d + 3) * 68 + t] = kv.w;
            float4 vv = *(const float4*)(Vp + (size_t)(kbase + t) * HD + dq * 4);
            *(float4*)&Vs[t * 64 + dq * 4] = vv;
        }
        __syncthreads();

        // S = (Q K^T) tile
        float s[8][4];
#pragma unroll
        for (int i = 0; i < 8; i++)
#pragma unroll
            for (int j = 0; j < 4; j++) s[i][j] = 0.0f;

#pragma unroll 8
        for (int d = 0; d < 64; d++) {
            float rM[8], rN[4];
            *(float4*)&rM[0] = *(const float4*)&Qs[d * 128 + tRow * 8];
            *(float4*)&rM[4] = *(const float4*)&Qs[d * 128 + tRow * 8 + 4];
            *(float4*)&rN[0] = *(const float4*)&Ks[d * 68 + tCol * 4];
#pragma unroll
            for (int i = 0; i < 8; i++)
#pragma unroll
                for (int j = 0; j < 4; j++)
                    s[i][j] = fmaf(rM[i], rN[j], s[i][j]);
        }

        // scale + causal mask
#pragma unroll
        for (int i = 0; i < 8; i++) {
            int tq = qbase + tRow * 8 + i;
#pragma unroll
            for (int j = 0; j < 4; j++) {
                int tk = kbase + tCol * 4 + j;
                s[i][j] = (tk <= tq) ? s[i][j] * scale : -1e30f;
            }
        }

        // online softmax (row stats across the 16 threadCols of each row group)
#pragma unroll
        for (int i = 0; i < 8; i++) {
            float mt = fmaxf(fmaxf(s[i][0], s[i][1]), fmaxf(s[i][2], s[i][3]));
#pragma unroll
            for (int off = 8; off > 0; off >>= 1)
                mt = fmaxf(mt, __shfl_xor_sync(0xffffffffu, mt, off));
            float mnew = fmaxf(mrow[i], mt);
            float corr = __expf(mrow[i] - mnew);
            float psum = 0.0f;
#pragma unroll
            for (int j = 0; j < 4; j++) {
                float p = __expf(s[i][j] - mnew);
                s[i][j] = p;
                psum += p;
            }
#pragma unroll
            for (int off = 8; off > 0; off >>= 1)
                psum += __shfl_xor_sync(0xffffffffu, psum, off);
            lrow[i] = lrow[i] * corr + psum;
            mrow[i] = mnew;
#pragma unroll
            for (int j = 0; j < 4; j++) O[i][j] *= corr;
        }

        // stage P (k-major) to smem
#pragma unroll
        for (int j = 0; j < 4; j++) {
            float4 a = make_float4(s[0][j], s[1][j], s[2][j], s[3][j]);
            float4 b = make_float4(s[4][j], s[5][j], s[6][j], s[7][j]);
            float* pp = &Ps[(tCol * 4 + j) * 128 + tRow * 8];
            *(float4*)pp       = a;
            *(float4*)(pp + 4) = b;
        }
        __syncthreads();

        // O += P @ V
#pragma unroll 8
        for (int k = 0; k < 64; k++) {
            float rM[8], rN[4];
            *(float4*)&rM[0] = *(const float4*)&Ps[k * 128 + tRow * 8];
            *(float4*)&rM[4] = *(const float4*)&Ps[k * 128 + tRow * 8 + 4];
            *(float4*)&rN[0] = *(const float4*)&Vs[k * 64 + tCol * 4];
#pragma unroll
            for (int i = 0; i < 8; i++)
#pragma unroll
                for (int j = 0; j < 4; j++)
                    O[i][j] = fmaf(rM[i], rN[j], O[i][j]);
        }
    }

    // Epilogue: Y[b][t][h*64 + d], normalize by l
    const int b = bh >> 4;
    const int h = bh & 15;
#pragma unroll
    for (int i = 0; i < 8; i++) {
        int t = qbase + tRow * 8 + i;
        float inv = 1.0f / lrow[i];
        float4 o = make_float4(O[i][0] * inv, O[i][1] * inv,
                               O[i][2] * inv, O[i][3] * inv);
        float* yp = Yg + ((size_t)(b * TT + t) * CC + h * HD + tCol * 4);
        *(float4*)yp = o;
    }
}

// ---------------------------------------------------------------------------
// Launch
// ---------------------------------------------------------------------------
extern "C" void kernel_launch(void* const* d_in, const int* in_sizes, int n_in,
                              void* d_out, int out_size)
{
    const float* x     = (const float*)d_in[0];
    const float* Wqkv  = (const float*)d_in[1];
    const float* bqkv  = (const float*)d_in[2];
    const float* Wproj = (const float*)d_in[3];
    const float* bproj = (const float*)d_in[4];
    float* out = (float*)d_out;

    (void)in_sizes; (void)n_in; (void)out_size;

    float* yp = nullptr;
    cudaGetSymbolAddress((void**)&yp, g_y);

    cudaFuncSetAttribute(attn_kernel,
                         cudaFuncAttributeMaxDynamicSharedMemorySize,
                         ATTN_SMEM_BYTES);

    // 1) QKV GEMM (+bias, scatter into per-head q/k/v)
    {
        dim3 grid(N_QKV / 128, MROWS / 128);   // (24, 32)
        sgemm_kernel<0><<<grid, 256>>>(x, Wqkv, bqkv, nullptr,
                                       MROWS, N_QKV, CC);
    }
    // 2) Causal flash attention
    {
        dim3 grid(TT / 128, BB * HH);          // (16, 32)
        attn_kernel<<<grid, 256, ATTN_SMEM_BYTES>>>(yp);
    }
    // 3) Output projection (+bias)
    {
        dim3 grid(CC / 128, MROWS / 128);      // (8, 32)
        sgemm_kernel<1><<<grid, 256>>>(yp, Wproj, bproj, out,
                                       MROWS, CC, CC);
    }
}

// round 3
// speedup vs baseline: 1.5698x; 1.5698x over previous
#include <cuda_runtime.h>
#include <math.h>
#include <stdint.h>

#define BB   2
#define TT   2048
#define CC   1024
#define HH   16
#define HD   64
#define MROWS (BB*TT)        // 4096
#define N_QKV (3*CC)         // 3072

// ---------------------------------------------------------------------------
// Scratch (device globals)
// ---------------------------------------------------------------------------
__device__ __align__(1024) float g_q[BB*HH*TT*HD];   // [B,H,T,HD]
__device__ __align__(1024) float g_k[BB*HH*TT*HD];
__device__ __align__(1024) float g_v[BB*HH*TT*HD];
__device__ __align__(1024) float g_y[MROWS*CC];      // attn out, PERMUTED tf32
__device__ __align__(1024) float g_xp[MROWS*CC];     // x, PERMUTED tf32
__device__ __align__(1024) float g_wtq[N_QKV*CC];    // Wqkv^T, PERMUTED tf32
__device__ __align__(1024) float g_wtp[CC*CC];       // Wproj^T, PERMUTED tf32

// ---------------------------------------------------------------------------
// Helpers
// ---------------------------------------------------------------------------
__device__ __forceinline__ float to_tf32(float x) {
    float r;
    asm("cvt.rna.tf32.f32 %0, %1;" : "=f"(r) : "f"(x));
    return r;
}

__device__ __forceinline__ uint32_t s2u(const void* p) {
    uint32_t a;
    asm("{ .reg .u64 t; cvta.to.shared.u64 t, %1; cvt.u32.u64 %0, t; }"
        : "=r"(a) : "l"(p));
    return a;
}

__device__ __forceinline__ void cp_async16(uint32_t dst, const float* src) {
    asm volatile("cp.async.cg.shared.global [%0], [%1], 16;"
                 :: "r"(dst), "l"(src) : "memory");
}

__device__ __forceinline__ float f4e(const float4& v, int i) {
    return i == 0 ? v.x : (i == 1 ? v.y : (i == 2 ? v.z : v.w));
}

__device__ __forceinline__ void mma_tf32(float d[4], float a0, float a1,
                                         float a2, float a3, float b0, float b1)
{
    asm volatile(
        "mma.sync.aligned.m16n8k8.row.col.f32.tf32.tf32.f32 "
        "{%0,%1,%2,%3}, {%4,%5,%6,%7}, {%8,%9}, {%0,%1,%2,%3};"
        : "+f"(d[0]), "+f"(d[1]), "+f"(d[2]), "+f"(d[3])
        : "r"(__float_as_uint(a0)), "r"(__float_as_uint(a1)),
          "r"(__float_as_uint(a2)), "r"(__float_as_uint(a3)),
          "r"(__float_as_uint(b0)), "r"(__float_as_uint(b1)));
}

// ---------------------------------------------------------------------------
// Prep kernels: permute K within 32-blocks (kperm = (k%4)*8 + k/4), tf32 round
// ---------------------------------------------------------------------------
__global__ void prep_A(const float* __restrict__ in, float* __restrict__ out,
                       int total4, int K)
{
    int idx = blockIdx.x * 256 + threadIdx.x;
    if (idx >= total4) return;
    int row = idx / (K / 4);
    int k   = (idx % (K / 4)) * 4;
    float4 v = *(const float4*)(in + (size_t)row * K + k);
    int kb = k & ~31;
    int q  = (k & 31) >> 2;
    float* o = out + (size_t)row * K + kb;
    o[q]      = to_tf32(v.x);
    o[8 + q]  = to_tf32(v.y);
    o[16 + q] = to_tf32(v.z);
    o[24 + q] = to_tf32(v.w);
}

// in [R][C] -> out [C][R] with perm on the R (=k) index, tf32 round
__global__ void transpose_perm(const float* __restrict__ in,
                               float* __restrict__ out, int R, int C)
{
    __shared__ float t[32][33];
    int c0 = blockIdx.x * 32, r0 = blockIdx.y * 32;
    int x = threadIdx.x, y = threadIdx.y;
#pragma unroll
    for (int i = 0; i < 32; i += 8)
        t[y + i][x] = in[(size_t)(r0 + y + i) * C + c0 + x];
    __syncthreads();
    int xp = (x & 3) * 8 + (x >> 2);
#pragma unroll
    for (int i = 0; i < 32; i += 8)
        out[(size_t)(c0 + y + i) * R + r0 + xp] = to_tf32(t[x][y + i]);
}

// ---------------------------------------------------------------------------
// TF32 mma.sync GEMM: D[M,N] = A[M,K=1024] @ Bt[N,K]^T (+bias)
// A, Bt are K-permuted tf32. CTA 128x128, k-block 32, 4-stage cp.async.
// 8 warps (4 along M x 2 along N), warp tile 32x64, m16n8k8 fragments.
// MODE 0: scatter into g_q/g_k/g_v.  MODE 1: row-major C.
// ---------------------------------------------------------------------------
#define GSTAGES 4
#define KB      32
#define APAD    36
#define TILE_F  (128*APAD)
#define GEMM_SMEM (GSTAGES*2*TILE_F*4)

__device__ __forceinline__ void g_load_stage(uint32_t sbase, int s,
                                             const float* Ag, const float* Bg,
                                             int k0, int tid)
{
    uint32_t base = sbase + (uint32_t)s * 2 * TILE_F * 4;
#pragma unroll
    for (int i = 0; i < 4; i++) {
        int f = tid + i * 256;          // 0..1023
        int row = f >> 3, c = f & 7;
        cp_async16(base + row * (APAD * 4) + c * 16,
                   Ag + (size_t)row * CC + k0 + c * 4);
        cp_async16(base + TILE_F * 4 + row * (APAD * 4) + c * 16,
                   Bg + (size_t)row * CC + k0 + c * 4);
    }
    asm volatile("cp.async.commit_group;" ::: "memory");
}

template <int MODE>
__global__ __launch_bounds__(256, 1)
void mma_gemm(const float* __restrict__ A, const float* __restrict__ Bt,
              const float* __restrict__ bias, float* __restrict__ Cout, int Nn)
{
    extern __shared__ __align__(16) float sm[];
    const uint32_t sbase = s2u(sm);
    const int tid  = threadIdx.x;
    const int lane = tid & 31;
    const int wid  = tid >> 5;
    const int wm   = wid & 3;           // 0..3 along M
    const int wn   = wid >> 2;          // 0..1 along N
    const int r    = lane >> 2;
    const int l4   = lane & 3;
    const int m0 = blockIdx.y * 128;
    const int n0 = blockIdx.x * 128;

    const float* Ag = A + (size_t)m0 * CC;
    const float* Bg = Bt + (size_t)n0 * CC;

    float acc[2][8][4];
#pragma unroll
    for (int mt = 0; mt < 2; mt++)
#pragma unroll
        for (int nt = 0; nt < 8; nt++)
#pragma unroll
            for (int j = 0; j < 4; j++) acc[mt][nt][j] = 0.0f;

    const int NIT = CC / KB;            // 32
#pragma unroll
    for (int s = 0; s < GSTAGES; s++)
        g_load_stage(sbase, s, Ag, Bg, s * KB, tid);

    for (int it = 0; it < NIT; it++) {
        if (it + GSTAGES <= NIT)
            asm volatile("cp.async.wait_group 3;" ::: "memory");
        else
            asm volatile("cp.async.wait_group 0;" ::: "memory");
        __syncthreads();

        const float* As = sm + (size_t)(it & (GSTAGES - 1)) * 2 * TILE_F;
        const float* Bs = As + TILE_F;

        float4 af[2][2][2];             // [mtile][rowhalf][lo/hi]
#pragma unroll
        for (int mt = 0; mt < 2; mt++) {
            const float* ap = As + (wm * 32 + mt * 16 + r) * APAD + l4 * 8;
            af[mt][0][0] = *(const float4*)ap;
            af[mt][0][1] = *(const float4*)(ap + 4);
            ap += 8 * APAD;
            af[mt][1][0] = *(const float4*)ap;
            af[mt][1][1] = *(const float4*)(ap + 4);
        }
        float4 bfr[8][2];
#pragma unroll
        for (int nt = 0; nt < 8; nt++) {
            const float* bp = Bs + (wn * 64 + nt * 8 + r) * APAD + l4 * 8;
            bfr[nt][0] = *(const float4*)bp;
            bfr[nt][1] = *(const float4*)(bp + 4);
        }

#pragma unroll
        for (int g = 0; g < 4; g++) {
            const int hi = g >> 1, e0 = (g & 1) * 2, e1 = e0 + 1;
#pragma unroll
            for (int mt = 0; mt < 2; mt++) {
                float a0 = f4e(af[mt][0][hi], e0);
                float a1 = f4e(af[mt][1][hi], e0);
                float a2 = f4e(af[mt][0][hi], e1);
                float a3 = f4e(af[mt][1][hi], e1);
#pragma unroll
                for (int nt = 0; nt < 8; nt++) {
                    float b0 = f4e(bfr[nt][hi], e0);
                    float b1 = f4e(bfr[nt][hi], e1);
                    mma_tf32(acc[mt][nt], a0, a1, a2, a3, b0, b1);
                }
            }
        }
        __syncthreads();
        if (it + GSTAGES < NIT)
            g_load_stage(sbase, it & (GSTAGES - 1), Ag, Bg, (it + GSTAGES) * KB, tid);
    }

    // Epilogue
#pragma unroll
    for (int mt = 0; mt < 2; mt++) {
#pragma unroll
        for (int nt = 0; nt < 8; nt++) {
            const int row = m0 + wm * 32 + mt * 16 + r;
            const int c   = n0 + wn * 64 + nt * 8 + 2 * l4;
            const float b0v = __ldg(bias + c);
            const float b1v = __ldg(bias + c + 1);
            float v00 = acc[mt][nt][0] + b0v, v01 = acc[mt][nt][1] + b1v;
            float v10 = acc[mt][nt][2] + b0v, v11 = acc[mt][nt][3] + b1v;
            if (MODE == 0) {
                const int sec = c >> 10;
                float* basep = (sec == 0) ? g_q : (sec == 1 ? g_k : g_v);
                const int cs = c & 1023, h = cs >> 6, d0 = cs & 63;
                {
                    const int b = row >> 11, t = row & 2047;
                    *(float2*)(basep + (((size_t)(b * HH + h) * TT + t) * HD + d0))
                        = make_float2(v00, v01);
                }
                {
                    const int row2 = row + 8;
                    const int b = row2 >> 11, t = row2 & 2047;
                    *(float2*)(basep + (((size_t)(b * HH + h) * TT + t) * HD + d0))
                        = make_float2(v10, v11);
                }
            } else {
                *(float2*)(Cout + (size_t)row * Nn + c)       = make_float2(v00, v01);
                *(float2*)(Cout + (size_t)(row + 8) * Nn + c) = make_float2(v10, v11);
            }
        }
    }
}

// ---------------------------------------------------------------------------
// Flash attention (fp32) — epilogue writes permuted tf32 y for the proj GEMM.
// ---------------------------------------------------------------------------
#define ATTN_SMEM_FLOATS (64*128 + 64*68 + 64*64 + 64*128)
#define ATTN_SMEM_BYTES  (ATTN_SMEM_FLOATS * 4)

__global__ __launch_bounds__(256)
void attn_kernel(float* __restrict__ Yg)
{
    extern __shared__ float sm[];
    float* Qs = sm;                   // [d][q]  stride 128
    float* Ks = Qs + 64 * 128;        // [d][t]  stride 68
    float* Vs = Ks + 64 * 68;         // [t][d]  stride 64
    float* Ps = Vs + 64 * 64;         // [k][q]  stride 128

    const int tid   = threadIdx.x;
    const int bh    = blockIdx.y;
    const int qbase = blockIdx.x * 128;
    const float scale = 0.125f;

    const float* Qp = g_q + (size_t)bh * TT * HD;
    const float* Kp = g_k + (size_t)bh * TT * HD;
    const float* Vp = g_v + (size_t)bh * TT * HD;

    for (int idx = tid; idx < 128 * 16; idx += 256) {
        int t  = idx >> 4;
        int dq = idx & 15;
        float4 v = *(const float4*)(Qp + (size_t)(qbase + t) * HD + dq * 4);
        int d = dq * 4;
        Qs[(d + 0) * 128 + t] = v.x;
        Qs[(d + 1) * 128 + t] = v.y;
        Qs[(d + 2) * 128 + t] = v.z;
        Qs[(d + 3) * 128 + t] = v.w;
    }

    const int tRow = tid >> 4;
    const int tCol = tid & 15;

    float O[8][4];
    float mrow[8], lrow[8];
#pragma unroll
    for (int i = 0; i < 8; i++) {
        mrow[i] = -1e30f;
        lrow[i] = 0.0f;
#pragma unroll
        for (int j = 0; j < 4; j++) O[i][j] = 0.0f;
    }

    const int ntiles = 2 * blockIdx.x + 2;
    for (int kt = 0; kt < ntiles; kt++) {
        const int kbase = kt * 64;
        __syncthreads();
        for (int idx = tid; idx < 64 * 16; idx += 256) {
            int t  = idx >> 4;
            int dq = idx & 15;
            float4 kv = *(const float4*)(Kp + (size_t)(kbase + t) * HD + dq * 4);
            int d = dq * 4;
            Ks[(d + 0) * 68 + t] = kv.x;
            Ks[(d + 1) * 68 + t] = kv.y;
            Ks[(d + 2) * 68 + t] = kv.z;
            Ks[(d + 3) * 68 + t] = kv.w;
            float4 vv = *(const float4*)(Vp + (size_t)(kbase + t) * HD + dq * 4);
            *(float4*)&Vs[t * 64 + dq * 4] = vv;
        }
        __syncthreads();

        float s[8][4];
#pragma unroll
        for (int i = 0; i < 8; i++)
#pragma unroll
            for (int j = 0; j < 4; j++) s[i][j] = 0.0f;

#pragma unroll 8
        for (int d = 0; d < 64; d++) {
            float rM[8], rN[4];
            *(float4*)&rM[0] = *(const float4*)&Qs[d * 128 + tRow * 8];
            *(float4*)&rM[4] = *(const float4*)&Qs[d * 128 + tRow * 8 + 4];
            *(float4*)&rN[0] = *(const float4*)&Ks[d * 68 + tCol * 4];
#pragma unroll
            for (int i = 0; i < 8; i++)
#pragma unroll
                for (int j = 0; j < 4; j++)
                    s[i][j] = fmaf(rM[i], rN[j], s[i][j]);
        }

#pragma unroll
        for (int i = 0; i < 8; i++) {
            int tq = qbase + tRow * 8 + i;
#pragma unroll
            for (int j = 0; j < 4; j++) {
                int tk = kbase + tCol * 4 + j;
                s[i][j] = (tk <= tq) ? s[i][j] * scale : -1e30f;
            }
        }

#pragma unroll
        for (int i = 0; i < 8; i++) {
            float mt = fmaxf(fmaxf(s[i][0], s[i][1]), fmaxf(s[i][2], s[i][3]));
#pragma unroll
            for (int off = 8; off > 0; off >>= 1)
                mt = fmaxf(mt, __shfl_xor_sync(0xffffffffu, mt, off));
            float mnew = fmaxf(mrow[i], mt);
            float corr = __expf(mrow[i] - mnew);
            float psum = 0.0f;
#pragma unroll
            for (int j = 0; j < 4; j++) {
                float p = __expf(s[i][j] - mnew);
                s[i][j] = p;
                psum += p;
            }
#pragma unroll
            for (int off = 8; off > 0; off >>= 1)
                psum += __shfl_xor_sync(0xffffffffu, psum, off);
            lrow[i] = lrow[i] * corr + psum;
            mrow[i] = mnew;
#pragma unroll
            for (int j = 0; j < 4; j++) O[i][j] *= corr;
        }

#pragma unroll
        for (int j = 0; j < 4; j++) {
            float4 a = make_float4(s[0][j], s[1][j], s[2][j], s[3][j]);
            float4 b = make_float4(s[4][j], s[5][j], s[6][j], s[7][j]);
            float* pp = &Ps[(tCol * 4 + j) * 128 + tRow * 8];
            *(float4*)pp       = a;
            *(float4*)(pp + 4) = b;
        }
        __syncthreads();

#pragma unroll 8
        for (int k = 0; k < 64; k++) {
            float rM[8], rN[4];
            *(float4*)&rM[0] = *(const float4*)&Ps[k * 128 + tRow * 8];
            *(float4*)&rM[4] = *(const float4*)&Ps[k * 128 + tRow * 8 + 4];
            *(float4*)&rN[0] = *(const float4*)&Vs[k * 64 + tCol * 4];
#pragma unroll
            for (int i = 0; i < 8; i++)
#pragma unroll
                for (int j = 0; j < 4; j++)
                    O[i][j] = fmaf(rM[i], rN[j], O[i][j]);
        }
    }

    // Epilogue: write y PERMUTED (k-block perm) + tf32-rounded for proj GEMM
    const int b = bh >> 4;
    const int h = bh & 15;
    const int cbase = h * HD + tCol * 4;       // multiple of 4
    const int kb = cbase & ~31;
    const int q  = (cbase & 31) >> 2;
#pragma unroll
    for (int i = 0; i < 8; i++) {
        int t = qbase + tRow * 8 + i;
        float inv = 1.0f / lrow[i];
        float* o = Yg + (size_t)(b * TT + t) * CC + kb;
        o[q]      = to_tf32(O[i][0] * inv);
        o[8 + q]  = to_tf32(O[i][1] * inv);
        o[16 + q] = to_tf32(O[i][2] * inv);
        o[24 + q] = to_tf32(O[i][3] * inv);
    }
}

// ---------------------------------------------------------------------------
// Launch
// ---------------------------------------------------------------------------
extern "C" void kernel_launch(void* const* d_in, const int* in_sizes, int n_in,
                              void* d_out, int out_size)
{
    const float* x     = (const float*)d_in[0];
    const float* Wqkv  = (const float*)d_in[1];
    const float* bqkv  = (const float*)d_in[2];
    const float* Wproj = (const float*)d_in[3];
    const float* bproj = (const float*)d_in[4];
    float* out = (float*)d_out;
    (void)in_sizes; (void)n_in; (void)out_size;

    float *yp, *xp, *wtq, *wtp;
    cudaGetSymbolAddress((void**)&yp,  g_y);
    cudaGetSymbolAddress((void**)&xp,  g_xp);
    cudaGetSymbolAddress((void**)&wtq, g_wtq);
    cudaGetSymbolAddress((void**)&wtp, g_wtp);

    cudaFuncSetAttribute(mma_gemm<0>, cudaFuncAttributeMaxDynamicSharedMemorySize, GEMM_SMEM);
    cudaFuncSetAttribute(mma_gemm<1>, cudaFuncAttributeMaxDynamicSharedMemorySize, GEMM_SMEM);
    cudaFuncSetAttribute(attn_kernel, cudaFuncAttributeMaxDynamicSharedMemorySize, ATTN_SMEM_BYTES);

    // Prep: permute/round x; transpose+permute/round weights
    {
        int total4 = MROWS * CC / 4;
        prep_A<<<(total4 + 255) / 256, 256>>>(x, xp, total4, CC);
        transpose_perm<<<dim3(N_QKV / 32, CC / 32), dim3(32, 8)>>>(Wqkv, wtq, CC, N_QKV);
        transpose_perm<<<dim3(CC / 32, CC / 32), dim3(32, 8)>>>(Wproj, wtp, CC, CC);
    }

    // 1) QKV GEMM (tf32 mma.sync) + bias + head scatter
    mma_gemm<0><<<dim3(N_QKV / 128, MROWS / 128), 256, GEMM_SMEM>>>(xp, wtq, bqkv, nullptr, N_QKV);

    // 2) Causal flash attention (fp32), writes permuted y
    attn_kernel<<<dim3(TT / 128, BB * HH), 256, ATTN_SMEM_BYTES>>>(yp);

    // 3) Output projection (tf32 mma.sync) + bias
    mma_gemm<1><<<dim3(CC / 128, MROWS / 128), 256, GEMM_SMEM>>>(yp, wtp, bproj, out, CC);
}

// round 4
// speedup vs baseline: 2.6476x; 1.6866x over previous
#include <cuda_runtime.h>
#include <math.h>
#include <stdint.h>

#define BB   2
#define TT   2048
#define CC   1024
#define HH   16
#define HD   64
#define MROWS (BB*TT)        // 4096
#define N_QKV (3*CC)         // 3072

// ---------------------------------------------------------------------------
// Scratch (device globals)
// ---------------------------------------------------------------------------
__device__ __align__(1024) float g_q[BB*HH*TT*HD];   // [B,H,T,HD]  tf32
__device__ __align__(1024) float g_k[BB*HH*TT*HD];   // [B,H,T,HD]  tf32
__device__ __align__(1024) float g_v[BB*HH*TT*HD];   // [B,H,HD,T]  tf32 (TRANSPOSED)
__device__ __align__(1024) float g_y[MROWS*CC];      // attn out, PERMUTED tf32
__device__ __align__(1024) float g_xp[MROWS*CC];     // x, PERMUTED tf32
__device__ __align__(1024) float g_wtq[N_QKV*CC];    // Wqkv^T, PERMUTED tf32
__device__ __align__(1024) float g_wtp[CC*CC];       // Wproj^T, PERMUTED tf32

// ---------------------------------------------------------------------------
// Helpers
// ---------------------------------------------------------------------------
__device__ __forceinline__ float to_tf32(float x) {
    float r;
    asm("cvt.rna.tf32.f32 %0, %1;" : "=f"(r) : "f"(x));
    return r;
}

__device__ __forceinline__ uint32_t s2u(const void* p) {
    uint32_t a;
    asm("{ .reg .u64 t; cvta.to.shared.u64 t, %1; cvt.u32.u64 %0, t; }"
        : "=r"(a) : "l"(p));
    return a;
}

__device__ __forceinline__ void cp_async16(uint32_t dst, const float* src) {
    asm volatile("cp.async.cg.shared.global [%0], [%1], 16;"
                 :: "r"(dst), "l"(src) : "memory");
}

__device__ __forceinline__ float f4e(const float4& v, int i) {
    return i == 0 ? v.x : (i == 1 ? v.y : (i == 2 ? v.z : v.w));
}

__device__ __forceinline__ void mma_tf32(float d[4], float a0, float a1,
                                         float a2, float a3, float b0, float b1)
{
    asm volatile(
        "mma.sync.aligned.m16n8k8.row.col.f32.tf32.tf32.f32 "
        "{%0,%1,%2,%3}, {%4,%5,%6,%7}, {%8,%9}, {%0,%1,%2,%3};"
        : "+f"(d[0]), "+f"(d[1]), "+f"(d[2]), "+f"(d[3])
        : "r"(__float_as_uint(a0)), "r"(__float_as_uint(a1)),
          "r"(__float_as_uint(a2)), "r"(__float_as_uint(a3)),
          "r"(__float_as_uint(b0)), "r"(__float_as_uint(b1)));
}

// ---------------------------------------------------------------------------
// Prep kernels: permute K within 32-blocks (kperm = (k%4)*8 + k/4), tf32 round
// ---------------------------------------------------------------------------
__global__ void prep_A(const float* __restrict__ in, float* __restrict__ out,
                       int total4, int K)
{
    int idx = blockIdx.x * 256 + threadIdx.x;
    if (idx >= total4) return;
    int row = idx / (K / 4);
    int k   = (idx % (K / 4)) * 4;
    float4 v = *(const float4*)(in + (size_t)row * K + k);
    int kb = k & ~31;
    int q  = (k & 31) >> 2;
    float* o = out + (size_t)row * K + kb;
    o[q]      = to_tf32(v.x);
    o[8 + q]  = to_tf32(v.y);
    o[16 + q] = to_tf32(v.z);
    o[24 + q] = to_tf32(v.w);
}

__global__ void transpose_perm(const float* __restrict__ in,
                               float* __restrict__ out, int R, int C)
{
    __shared__ float t[32][33];
    int c0 = blockIdx.x * 32, r0 = blockIdx.y * 32;
    int x = threadIdx.x, y = threadIdx.y;
#pragma unroll
    for (int i = 0; i < 32; i += 8)
        t[y + i][x] = in[(size_t)(r0 + y + i) * C + c0 + x];
    __syncthreads();
    int xp = (x & 3) * 8 + (x >> 2);
#pragma unroll
    for (int i = 0; i < 32; i += 8)
        out[(size_t)(c0 + y + i) * R + r0 + xp] = to_tf32(t[x][y + i]);
}

// ---------------------------------------------------------------------------
// TF32 mma.sync GEMM (round-3, passing). MODE 0 epilogue now tf32-rounds and
// stores V transposed ([B,H,HD,T]).
// ---------------------------------------------------------------------------
#define GSTAGES 4
#define KB      32
#define APAD    36
#define TILE_F  (128*APAD)
#define GEMM_SMEM (GSTAGES*2*TILE_F*4)

__device__ __forceinline__ void g_load_stage(uint32_t sbase, int s,
                                             const float* Ag, const float* Bg,
                                             int k0, int tid)
{
    uint32_t base = sbase + (uint32_t)s * 2 * TILE_F * 4;
#pragma unroll
    for (int i = 0; i < 4; i++) {
        int f = tid + i * 256;
        int row = f >> 3, c = f & 7;
        cp_async16(base + row * (APAD * 4) + c * 16,
                   Ag + (size_t)row * CC + k0 + c * 4);
        cp_async16(base + TILE_F * 4 + row * (APAD * 4) + c * 16,
                   Bg + (size_t)row * CC + k0 + c * 4);
    }
    asm volatile("cp.async.commit_group;" ::: "memory");
}

template <int MODE>
__global__ __launch_bounds__(256, 1)
void mma_gemm(const float* __restrict__ A, const float* __restrict__ Bt,
              const float* __restrict__ bias, float* __restrict__ Cout, int Nn)
{
    extern __shared__ __align__(16) float sm[];
    const uint32_t sbase = s2u(sm);
    const int tid  = threadIdx.x;
    const int lane = tid & 31;
    const int wid  = tid >> 5;
    const int wm   = wid & 3;
    const int wn   = wid >> 2;
    const int r    = lane >> 2;
    const int l4   = lane & 3;
    const int m0 = blockIdx.y * 128;
    const int n0 = blockIdx.x * 128;

    const float* Ag = A + (size_t)m0 * CC;
    const float* Bg = Bt + (size_t)n0 * CC;

    float acc[2][8][4];
#pragma unroll
    for (int mt = 0; mt < 2; mt++)
#pragma unroll
        for (int nt = 0; nt < 8; nt++)
#pragma unroll
            for (int j = 0; j < 4; j++) acc[mt][nt][j] = 0.0f;

    const int NIT = CC / KB;
#pragma unroll
    for (int s = 0; s < GSTAGES; s++)
        g_load_stage(sbase, s, Ag, Bg, s * KB, tid);

    for (int it = 0; it < NIT; it++) {
        if (it + GSTAGES <= NIT)
            asm volatile("cp.async.wait_group 3;" ::: "memory");
        else
            asm volatile("cp.async.wait_group 0;" ::: "memory");
        __syncthreads();

        const float* As = sm + (size_t)(it & (GSTAGES - 1)) * 2 * TILE_F;
        const float* Bs = As + TILE_F;

        float4 af[2][2][2];
#pragma unroll
        for (int mt = 0; mt < 2; mt++) {
            const float* ap = As + (wm * 32 + mt * 16 + r) * APAD + l4 * 8;
            af[mt][0][0] = *(const float4*)ap;
            af[mt][0][1] = *(const float4*)(ap + 4);
            ap += 8 * APAD;
            af[mt][1][0] = *(const float4*)ap;
            af[mt][1][1] = *(const float4*)(ap + 4);
        }
        float4 bfr[8][2];
#pragma unroll
        for (int nt = 0; nt < 8; nt++) {
            const float* bp = Bs + (wn * 64 + nt * 8 + r) * APAD + l4 * 8;
            bfr[nt][0] = *(const float4*)bp;
            bfr[nt][1] = *(const float4*)(bp + 4);
        }

#pragma unroll
        for (int g = 0; g < 4; g++) {
            const int hi = g >> 1, e0 = (g & 1) * 2, e1 = e0 + 1;
#pragma unroll
            for (int mt = 0; mt < 2; mt++) {
                float a0 = f4e(af[mt][0][hi], e0);
                float a1 = f4e(af[mt][1][hi], e0);
                float a2 = f4e(af[mt][0][hi], e1);
                float a3 = f4e(af[mt][1][hi], e1);
#pragma unroll
                for (int nt = 0; nt < 8; nt++) {
                    float b0 = f4e(bfr[nt][hi], e0);
                    float b1 = f4e(bfr[nt][hi], e1);
                    mma_tf32(acc[mt][nt], a0, a1, a2, a3, b0, b1);
                }
            }
        }
        __syncthreads();
        if (it + GSTAGES < NIT)
            g_load_stage(sbase, it & (GSTAGES - 1), Ag, Bg, (it + GSTAGES) * KB, tid);
    }

#pragma unroll
    for (int mt = 0; mt < 2; mt++) {
#pragma unroll
        for (int nt = 0; nt < 8; nt++) {
            const int row = m0 + wm * 32 + mt * 16 + r;
            const int c   = n0 + wn * 64 + nt * 8 + 2 * l4;
            const float b0v = __ldg(bias + c);
            const float b1v = __ldg(bias + c + 1);
            float v00 = acc[mt][nt][0] + b0v, v01 = acc[mt][nt][1] + b1v;
            float v10 = acc[mt][nt][2] + b0v, v11 = acc[mt][nt][3] + b1v;
            if (MODE == 0) {
                const int sec = c >> 10;
                const int cs = c & 1023, h = cs >> 6, d0 = cs & 63;
                const int b  = row >> 11;
                const int t0 = row & 2047;
                const int t1 = (row + 8) & 2047;
                if (sec == 2) {
                    // V transposed [B,H,HD,T], tf32-rounded
                    float* vb = g_v + ((size_t)(b * HH + h) * HD) * TT;
                    vb[(size_t)d0 * TT + t0]       = to_tf32(v00);
                    vb[(size_t)(d0 + 1) * TT + t0] = to_tf32(v01);
                    vb[(size_t)d0 * TT + t1]       = to_tf32(v10);
                    vb[(size_t)(d0 + 1) * TT + t1] = to_tf32(v11);
                } else {
                    float* basep = (sec == 0) ? g_q : g_k;
                    float* p0 = basep + (((size_t)(b * HH + h) * TT + t0) * HD + d0);
                    float* p1 = basep + (((size_t)(b * HH + h) * TT + t1) * HD + d0);
                    *(float2*)p0 = make_float2(to_tf32(v00), to_tf32(v01));
                    *(float2*)p1 = make_float2(to_tf32(v10), to_tf32(v11));
                }
            } else {
                *(float2*)(Cout + (size_t)row * Nn + c)       = make_float2(v00, v01);
                *(float2*)(Cout + (size_t)(row + 8) * Nn + c) = make_float2(v10, v11);
            }
        }
    }
}

// ---------------------------------------------------------------------------
// Flash attention on tf32 mma.sync.
// CTA: 256 thr (8 warps), q-tile 128 (warp w owns rows w*16..w*16+15), k-tile 64.
// smem: Ks[64][72] (d-permuted), VTs[64][72] (tk-permuted), Ps[128][72]
// (per-warp P tiles; doubles as Q staging before the main loop).
// ---------------------------------------------------------------------------
#define AT_PAD  72
#define AT_SMEM ((64*AT_PAD*2 + 128*AT_PAD)*4)

__global__ __launch_bounds__(256, 1)
void attn_mma(float* __restrict__ Yg)
{
    extern __shared__ __align__(16) float smf[];
    float* Ksm = smf;                       // [64][72]
    float* VTs = smf + 64 * AT_PAD;         // [64][72]
    float* Ps  = smf + 128 * AT_PAD;        // [128][72]

    const int tid  = threadIdx.x;
    const int lane = tid & 31;
    const int w    = tid >> 5;
    const int r    = lane >> 2;
    const int l4   = lane & 3;
    const int bh   = blockIdx.y;
    const int qbase = blockIdx.x * 128;
    const float scale = 0.125f;

    const float* Qp  = g_q + (size_t)bh * TT * HD;
    const float* Kp  = g_k + (size_t)bh * TT * HD;
    const float* Vtp = g_v + (size_t)bh * HD * TT;

    // Stage Q (128x64) into Ps with intra-8 d-permute
#pragma unroll
    for (int i = 0; i < 8; i++) {
        int f = tid + i * 256;
        int t = f >> 4, dq = f & 15;
        float4 v = *(const float4*)(Qp + (size_t)(qbase + t) * HD + dq * 4);
        float* dst = Ps + t * AT_PAD + (dq >> 1) * 8 + (dq & 1);
        dst[0] = v.x; dst[2] = v.y; dst[4] = v.z; dst[6] = v.w;
    }
    __syncthreads();

    // Q fragments (held in registers for the whole kernel)
    float aq[8][4];
    {
        const float* q0 = Ps + (w * 16 + r) * AT_PAD + l4 * 2;
        const float* q1 = q0 + 8 * AT_PAD;
#pragma unroll
        for (int k = 0; k < 8; k++) {
            float2 f = *(const float2*)(q0 + k * 8);
            float2 g = *(const float2*)(q1 + k * 8);
            aq[k][0] = f.x; aq[k][1] = g.x; aq[k][2] = f.y; aq[k][3] = g.y;
        }
    }

    float O[8][4];
#pragma unroll
    for (int nt = 0; nt < 8; nt++)
#pragma unroll
        for (int j = 0; j < 4; j++) O[nt][j] = 0.0f;
    float m0v = -1e30f, m1v = -1e30f, l0v = 0.0f, l1v = 0.0f;

    const int tq0 = qbase + w * 16 + r;
    const int tq1 = tq0 + 8;
    const int ntiles = 2 * blockIdx.x + 2;
    float* pw = Ps + (w * 16) * AT_PAD;
    const int pos0 = (l4 < 2) ? l4 * 4 : (l4 - 2) * 4 + 1;

    for (int kt = 0; kt < ntiles; kt++) {
        const int kbase = kt * 64;
        __syncthreads();
        // K tile -> Ksm (d-permuted)
#pragma unroll
        for (int i = 0; i < 4; i++) {
            int f = tid + i * 256;
            int t = f >> 4, dq = f & 15;
            float4 v = *(const float4*)(Kp + (size_t)(kbase + t) * HD + dq * 4);
            float* dst = Ksm + t * AT_PAD + (dq >> 1) * 8 + (dq & 1);
            dst[0] = v.x; dst[2] = v.y; dst[4] = v.z; dst[6] = v.w;
        }
        // V^T tile -> VTs (tk-permuted)
#pragma unroll
        for (int i = 0; i < 4; i++) {
            int f = tid + i * 256;
            int d = f >> 4, t4 = f & 15;
            float4 v = *(const float4*)(Vtp + (size_t)d * TT + kbase + t4 * 4);
            float* dst = VTs + d * AT_PAD + (t4 >> 1) * 8 + (t4 & 1);
            dst[0] = v.x; dst[2] = v.y; dst[4] = v.z; dst[6] = v.w;
        }
        __syncthreads();

        // S = Q K^T
        float s[8][4];
#pragma unroll
        for (int nt = 0; nt < 8; nt++) {
#pragma unroll
            for (int j = 0; j < 4; j++) s[nt][j] = 0.0f;
            const float* kp = Ksm + (nt * 8 + r) * AT_PAD + l4 * 2;
#pragma unroll
            for (int k = 0; k < 8; k++) {
                float2 b = *(const float2*)(kp + k * 8);
                mma_tf32(s[nt], aq[k][0], aq[k][1], aq[k][2], aq[k][3], b.x, b.y);
            }
        }

        // scale + causal mask
        if (kbase + 63 <= qbase + w * 16) {
#pragma unroll
            for (int nt = 0; nt < 8; nt++)
#pragma unroll
                for (int j = 0; j < 4; j++) s[nt][j] *= scale;
        } else {
#pragma unroll
            for (int nt = 0; nt < 8; nt++) {
                int tk = kbase + nt * 8 + 2 * l4;
                s[nt][0] = (tk     <= tq0) ? s[nt][0] * scale : -1e30f;
                s[nt][1] = (tk + 1 <= tq0) ? s[nt][1] * scale : -1e30f;
                s[nt][2] = (tk     <= tq1) ? s[nt][2] * scale : -1e30f;
                s[nt][3] = (tk + 1 <= tq1) ? s[nt][3] * scale : -1e30f;
            }
        }

        // online softmax (rows tq0, tq1)
        float ml0 = -1e30f, ml1 = -1e30f;
#pragma unroll
        for (int nt = 0; nt < 8; nt++) {
            ml0 = fmaxf(ml0, fmaxf(s[nt][0], s[nt][1]));
            ml1 = fmaxf(ml1, fmaxf(s[nt][2], s[nt][3]));
        }
        ml0 = fmaxf(ml0, __shfl_xor_sync(0xffffffffu, ml0, 1));
        ml0 = fmaxf(ml0, __shfl_xor_sync(0xffffffffu, ml0, 2));
        ml1 = fmaxf(ml1, __shfl_xor_sync(0xffffffffu, ml1, 1));
        ml1 = fmaxf(ml1, __shfl_xor_sync(0xffffffffu, ml1, 2));
        float mn0 = fmaxf(m0v, ml0), mn1 = fmaxf(m1v, ml1);
        float c0 = __expf(m0v - mn0), c1 = __expf(m1v - mn1);
        float ps0 = 0.0f, ps1 = 0.0f;
#pragma unroll
        for (int nt = 0; nt < 8; nt++) {
            s[nt][0] = __expf(s[nt][0] - mn0); ps0 += s[nt][0];
            s[nt][1] = __expf(s[nt][1] - mn0); ps0 += s[nt][1];
            s[nt][2] = __expf(s[nt][2] - mn1); ps1 += s[nt][2];
            s[nt][3] = __expf(s[nt][3] - mn1); ps1 += s[nt][3];
        }
        ps0 += __shfl_xor_sync(0xffffffffu, ps0, 1);
        ps0 += __shfl_xor_sync(0xffffffffu, ps0, 2);
        ps1 += __shfl_xor_sync(0xffffffffu, ps1, 1);
        ps1 += __shfl_xor_sync(0xffffffffu, ps1, 2);
        l0v = l0v * c0 + ps0; m0v = mn0;
        l1v = l1v * c1 + ps1; m1v = mn1;
#pragma unroll
        for (int nt = 0; nt < 8; nt++) {
            O[nt][0] *= c0; O[nt][1] *= c0;
            O[nt][2] *= c1; O[nt][3] *= c1;
        }

        // P -> per-warp smem (tk-permuted, tf32-rounded)
#pragma unroll
        for (int nt = 0; nt < 8; nt++) {
            float* p0 = pw + r * AT_PAD + nt * 8 + pos0;
            float* p1 = pw + (r + 8) * AT_PAD + nt * 8 + pos0;
            p0[0] = to_tf32(s[nt][0]); p0[2] = to_tf32(s[nt][1]);
            p1[0] = to_tf32(s[nt][2]); p1[2] = to_tf32(s[nt][3]);
        }
        __syncwarp();

        // P fragments
        float pa[8][4];
        {
            const float* p0 = pw + r * AT_PAD + l4 * 2;
            const float* p1 = p0 + 8 * AT_PAD;
#pragma unroll
            for (int k = 0; k < 8; k++) {
                float2 f = *(const float2*)(p0 + k * 8);
                float2 g = *(const float2*)(p1 + k * 8);
                pa[k][0] = f.x; pa[k][1] = g.x; pa[k][2] = f.y; pa[k][3] = g.y;
            }
        }

        // O += P V
#pragma unroll
        for (int nt = 0; nt < 8; nt++) {
            const float* vp = VTs + (nt * 8 + r) * AT_PAD + l4 * 2;
#pragma unroll
            for (int k = 0; k < 8; k++) {
                float2 b = *(const float2*)(vp + k * 8);
                mma_tf32(O[nt], pa[k][0], pa[k][1], pa[k][2], pa[k][3], b.x, b.y);
            }
        }
    }

    // Epilogue: normalize, write y permuted+tf32 for proj GEMM
    const int b = bh >> 4;
    const int h = bh & 15;
    const int hb = h * 64;
    const float inv0 = 1.0f / l0v, inv1 = 1.0f / l1v;
    float* y0 = Yg + (size_t)(b * TT + tq0) * CC;
    float* y1 = Yg + (size_t)(b * TT + tq1) * CC;
#pragma unroll
    for (int nt = 0; nt < 8; nt++) {
        int c = hb + nt * 8 + 2 * l4;
        int base = c & ~31;
        int k5 = c & 31, k51 = (c + 1) & 31;
        int p0 = (k5 & 3) * 8 + (k5 >> 2);
        int p1 = (k51 & 3) * 8 + (k51 >> 2);
        y0[base + p0] = to_tf32(O[nt][0] * inv0);
        y0[base + p1] = to_tf32(O[nt][1] * inv0);
        y1[base + p0] = to_tf32(O[nt][2] * inv1);
        y1[base + p1] = to_tf32(O[nt][3] * inv1);
    }
}

// ---------------------------------------------------------------------------
// Launch
// ---------------------------------------------------------------------------
extern "C" void kernel_launch(void* const* d_in, const int* in_sizes, int n_in,
                              void* d_out, int out_size)
{
    const float* x     = (const float*)d_in[0];
    const float* Wqkv  = (const float*)d_in[1];
    const float* bqkv  = (const float*)d_in[2];
    const float* Wproj = (const float*)d_in[3];
    const float* bproj = (const float*)d_in[4];
    float* out = (float*)d_out;
    (void)in_sizes; (void)n_in; (void)out_size;

    float *yp, *xp, *wtq, *wtp;
    cudaGetSymbolAddress((void**)&yp,  g_y);
    cudaGetSymbolAddress((void**)&xp,  g_xp);
    cudaGetSymbolAddress((void**)&wtq, g_wtq);
    cudaGetSymbolAddress((void**)&wtp, g_wtp);

    cudaFuncSetAttribute(mma_gemm<0>, cudaFuncAttributeMaxDynamicSharedMemorySize, GEMM_SMEM);
    cudaFuncSetAttribute(mma_gemm<1>, cudaFuncAttributeMaxDynamicSharedMemorySize, GEMM_SMEM);
    cudaFuncSetAttribute(attn_mma,    cudaFuncAttributeMaxDynamicSharedMemorySize, AT_SMEM);

    {
        int total4 = MROWS * CC / 4;
        prep_A<<<(total4 + 255) / 256, 256>>>(x, xp, total4, CC);
        transpose_perm<<<dim3(N_QKV / 32, CC / 32), dim3(32, 8)>>>(Wqkv, wtq, CC, N_QKV);
        transpose_perm<<<dim3(CC / 32, CC / 32), dim3(32, 8)>>>(Wproj, wtp, CC, CC);
    }

    // 1) QKV GEMM (tf32) + bias + head scatter (q,k natural; v transposed)
    mma_gemm<0><<<dim3(N_QKV / 128, MROWS / 128), 256, GEMM_SMEM>>>(xp, wtq, bqkv, nullptr, N_QKV);

    // 2) Causal flash attention (tf32 mma), writes permuted y
    attn_mma<<<dim3(TT / 128, BB * HH), 256, AT_SMEM>>>(yp);

    // 3) Output projection (tf32) + bias
    mma_gemm<1><<<dim3(CC / 128, MROWS / 128), 256, GEMM_SMEM>>>(yp, wtp, bproj, out, CC);
}

// round 5
// speedup vs baseline: 2.8556x; 1.0785x over previous
#include <cuda_runtime.h>
#include <math.h>
#include <stdint.h>

#define BB   2
#define TT   2048
#define CC   1024
#define HH   16
#define HD   64
#define MROWS (BB*TT)        // 4096
#define N_QKV (3*CC)         // 3072

// ---------------------------------------------------------------------------
// Scratch (device globals)
// ---------------------------------------------------------------------------
__device__ __align__(1024) float g_q[BB*HH*TT*HD];   // [B,H,T,HD]  tf32
__device__ __align__(1024) float g_k[BB*HH*TT*HD];   // [B,H,T,HD]  tf32
__device__ __align__(1024) float g_v[BB*HH*TT*HD];   // [B,H,HD,T]  tf32 (TRANSPOSED)
__device__ __align__(1024) float g_y[MROWS*CC];      // attn out, PERMUTED tf32
__device__ __align__(1024) float g_xp[MROWS*CC];     // x, PERMUTED tf32
__device__ __align__(1024) float g_wtq[N_QKV*CC];    // Wqkv^T, PERMUTED tf32
__device__ __align__(1024) float g_wtp[CC*CC];       // Wproj^T, PERMUTED tf32

// ---------------------------------------------------------------------------
// Helpers
// ---------------------------------------------------------------------------
__device__ __forceinline__ float to_tf32(float x) {
    float r;
    asm("cvt.rna.tf32.f32 %0, %1;" : "=f"(r) : "f"(x));
    return r;
}

__device__ __forceinline__ uint32_t s2u(const void* p) {
    uint32_t a;
    asm("{ .reg .u64 t; cvta.to.shared.u64 t, %1; cvt.u32.u64 %0, t; }"
        : "=r"(a) : "l"(p));
    return a;
}

__device__ __forceinline__ void cp_async16(uint32_t dst, const float* src) {
    asm volatile("cp.async.cg.shared.global [%0], [%1], 16;"
                 :: "r"(dst), "l"(src) : "memory");
}

__device__ __forceinline__ float f4e(const float4& v, int i) {
    return i == 0 ? v.x : (i == 1 ? v.y : (i == 2 ? v.z : v.w));
}

__device__ __forceinline__ void mma_tf32(float d[4], float a0, float a1,
                                         float a2, float a3, float b0, float b1)
{
    asm volatile(
        "mma.sync.aligned.m16n8k8.row.col.f32.tf32.tf32.f32 "
        "{%0,%1,%2,%3}, {%4,%5,%6,%7}, {%8,%9}, {%0,%1,%2,%3};"
        : "+f"(d[0]), "+f"(d[1]), "+f"(d[2]), "+f"(d[3])
        : "r"(__float_as_uint(a0)), "r"(__float_as_uint(a1)),
          "r"(__float_as_uint(a2)), "r"(__float_as_uint(a3)),
          "r"(__float_as_uint(b0)), "r"(__float_as_uint(b1)));
}

// ---------------------------------------------------------------------------
// Prep kernels: permute K within 32-blocks (kperm = (k%4)*8 + k/4), tf32 round
// ---------------------------------------------------------------------------
__global__ void prep_A(const float* __restrict__ in, float* __restrict__ out,
                       int total4, int K)
{
    int idx = blockIdx.x * 256 + threadIdx.x;
    if (idx >= total4) return;
    int row = idx / (K / 4);
    int k   = (idx % (K / 4)) * 4;
    float4 v = *(const float4*)(in + (size_t)row * K + k);
    int kb = k & ~31;
    int q  = (k & 31) >> 2;
    float* o = out + (size_t)row * K + kb;
    o[q]      = to_tf32(v.x);
    o[8 + q]  = to_tf32(v.y);
    o[16 + q] = to_tf32(v.z);
    o[24 + q] = to_tf32(v.w);
}

__global__ void transpose_perm(const float* __restrict__ in,
                               float* __restrict__ out, int R, int C)
{
    __shared__ float t[32][33];
    int c0 = blockIdx.x * 32, r0 = blockIdx.y * 32;
    int x = threadIdx.x, y = threadIdx.y;
#pragma unroll
    for (int i = 0; i < 32; i += 8)
        t[y + i][x] = in[(size_t)(r0 + y + i) * C + c0 + x];
    __syncthreads();
    int xp = (x & 3) * 8 + (x >> 2);
#pragma unroll
    for (int i = 0; i < 32; i += 8)
        out[(size_t)(c0 + y + i) * R + r0 + xp] = to_tf32(t[x][y + i]);
}

// ---------------------------------------------------------------------------
// TF32 mma.sync GEMM. 3-stage cp.async pipeline, 2 CTAs/SM (regs<=128).
// ---------------------------------------------------------------------------
#define GSTAGES 3
#define KB      32
#define APAD    36
#define TILE_F  (128*APAD)
#define GEMM_SMEM (GSTAGES*2*TILE_F*4)

__device__ __forceinline__ void g_load_stage(uint32_t sbase, int s,
                                             const float* Ag, const float* Bg,
                                             int k0, int tid)
{
    uint32_t base = sbase + (uint32_t)s * 2 * TILE_F * 4;
#pragma unroll
    for (int i = 0; i < 4; i++) {
        int f = tid + i * 256;
        int row = f >> 3, c = f & 7;
        cp_async16(base + row * (APAD * 4) + c * 16,
                   Ag + (size_t)row * CC + k0 + c * 4);
        cp_async16(base + TILE_F * 4 + row * (APAD * 4) + c * 16,
                   Bg + (size_t)row * CC + k0 + c * 4);
    }
    asm volatile("cp.async.commit_group;" ::: "memory");
}

template <int MODE>
__global__ __launch_bounds__(256, 2)
void mma_gemm(const float* __restrict__ A, const float* __restrict__ Bt,
              const float* __restrict__ bias, float* __restrict__ Cout, int Nn)
{
    extern __shared__ __align__(16) float sm[];
    const uint32_t sbase = s2u(sm);
    const int tid  = threadIdx.x;
    const int lane = tid & 31;
    const int wid  = tid >> 5;
    const int wm   = wid & 3;
    const int wn   = wid >> 2;
    const int r    = lane >> 2;
    const int l4   = lane & 3;
    const int m0 = blockIdx.y * 128;
    const int n0 = blockIdx.x * 128;

    const float* Ag = A + (size_t)m0 * CC;
    const float* Bg = Bt + (size_t)n0 * CC;

    float acc[2][8][4];
#pragma unroll
    for (int mt = 0; mt < 2; mt++)
#pragma unroll
        for (int nt = 0; nt < 8; nt++)
#pragma unroll
            for (int j = 0; j < 4; j++) acc[mt][nt][j] = 0.0f;

    const int NIT = CC / KB;
#pragma unroll
    for (int s = 0; s < GSTAGES; s++)
        g_load_stage(sbase, s, Ag, Bg, s * KB, tid);

    for (int it = 0; it < NIT; it++) {
        if (it + GSTAGES <= NIT)
            asm volatile("cp.async.wait_group %0;" :: "n"(GSTAGES - 1) : "memory");
        else
            asm volatile("cp.async.wait_group 0;" ::: "memory");
        __syncthreads();

        const float* As = sm + (size_t)((it * 2) % (GSTAGES * 2)) * TILE_F;
        const float* Bs = As + TILE_F;

        float4 af[2][2][2];
#pragma unroll
        for (int mt = 0; mt < 2; mt++) {
            const float* ap = As + (wm * 32 + mt * 16 + r) * APAD + l4 * 8;
            af[mt][0][0] = *(const float4*)ap;
            af[mt][0][1] = *(const float4*)(ap + 4);
            ap += 8 * APAD;
            af[mt][1][0] = *(const float4*)ap;
            af[mt][1][1] = *(const float4*)(ap + 4);
        }
        float4 bfr[8][2];
#pragma unroll
        for (int nt = 0; nt < 8; nt++) {
            const float* bp = Bs + (wn * 64 + nt * 8 + r) * APAD + l4 * 8;
            bfr[nt][0] = *(const float4*)bp;
            bfr[nt][1] = *(const float4*)(bp + 4);
        }

#pragma unroll
        for (int g = 0; g < 4; g++) {
            const int hi = g >> 1, e0 = (g & 1) * 2, e1 = e0 + 1;
#pragma unroll
            for (int mt = 0; mt < 2; mt++) {
                float a0 = f4e(af[mt][0][hi], e0);
                float a1 = f4e(af[mt][1][hi], e0);
                float a2 = f4e(af[mt][0][hi], e1);
                float a3 = f4e(af[mt][1][hi], e1);
#pragma unroll
                for (int nt = 0; nt < 8; nt++) {
                    float b0 = f4e(bfr[nt][hi], e0);
                    float b1 = f4e(bfr[nt][hi], e1);
                    mma_tf32(acc[mt][nt], a0, a1, a2, a3, b0, b1);
                }
            }
        }
        __syncthreads();
        if (it + GSTAGES < NIT)
            g_load_stage(sbase, (it + GSTAGES) % GSTAGES, Ag, Bg,
                         (it + GSTAGES) * KB, tid);
    }

#pragma unroll
    for (int mt = 0; mt < 2; mt++) {
#pragma unroll
        for (int nt = 0; nt < 8; nt++) {
            const int row = m0 + wm * 32 + mt * 16 + r;
            const int c   = n0 + wn * 64 + nt * 8 + 2 * l4;
            const float b0v = __ldg(bias + c);
            const float b1v = __ldg(bias + c + 1);
            float v00 = acc[mt][nt][0] + b0v, v01 = acc[mt][nt][1] + b1v;
            float v10 = acc[mt][nt][2] + b0v, v11 = acc[mt][nt][3] + b1v;
            if (MODE == 0) {
                const int sec = c >> 10;
                const int cs = c & 1023, h = cs >> 6, d0 = cs & 63;
                const int b  = row >> 11;
                const int t0 = row & 2047;
                const int t1 = (row + 8) & 2047;
                if (sec == 2) {
                    float* vb = g_v + ((size_t)(b * HH + h) * HD) * TT;
                    vb[(size_t)d0 * TT + t0]       = to_tf32(v00);
                    vb[(size_t)(d0 + 1) * TT + t0] = to_tf32(v01);
                    vb[(size_t)d0 * TT + t1]       = to_tf32(v10);
                    vb[(size_t)(d0 + 1) * TT + t1] = to_tf32(v11);
                } else {
                    float* basep = (sec == 0) ? g_q : g_k;
                    float* p0 = basep + (((size_t)(b * HH + h) * TT + t0) * HD + d0);
                    float* p1 = basep + (((size_t)(b * HH + h) * TT + t1) * HD + d0);
                    *(float2*)p0 = make_float2(to_tf32(v00), to_tf32(v01));
                    *(float2*)p1 = make_float2(to_tf32(v10), to_tf32(v11));
                }
            } else {
                *(float2*)(Cout + (size_t)row * Nn + c)       = make_float2(v00, v01);
                *(float2*)(Cout + (size_t)(row + 8) * Nn + c) = make_float2(v10, v11);
            }
        }
    }
}

// ---------------------------------------------------------------------------
// Flash attention on tf32 mma.sync (round-4, passing — unchanged).
// ---------------------------------------------------------------------------
#define AT_PAD  72
#define AT_SMEM ((64*AT_PAD*2 + 128*AT_PAD)*4)

__global__ __launch_bounds__(256, 1)
void attn_mma(float* __restrict__ Yg)
{
    extern __shared__ __align__(16) float smf[];
    float* Ksm = smf;                       // [64][72]
    float* VTs = smf + 64 * AT_PAD;         // [64][72]
    float* Ps  = smf + 128 * AT_PAD;        // [128][72]

    const int tid  = threadIdx.x;
    const int lane = tid & 31;
    const int w    = tid >> 5;
    const int r    = lane >> 2;
    const int l4   = lane & 3;
    const int bh   = blockIdx.y;
    const int qbase = blockIdx.x * 128;
    const float scale = 0.125f;

    const float* Qp  = g_q + (size_t)bh * TT * HD;
    const float* Kp  = g_k + (size_t)bh * TT * HD;
    const float* Vtp = g_v + (size_t)bh * HD * TT;

#pragma unroll
    for (int i = 0; i < 8; i++) {
        int f = tid + i * 256;
        int t = f >> 4, dq = f & 15;
        float4 v = *(const float4*)(Qp + (size_t)(qbase + t) * HD + dq * 4);
        float* dst = Ps + t * AT_PAD + (dq >> 1) * 8 + (dq & 1);
        dst[0] = v.x; dst[2] = v.y; dst[4] = v.z; dst[6] = v.w;
    }
    __syncthreads();

    float aq[8][4];
    {
        const float* q0 = Ps + (w * 16 + r) * AT_PAD + l4 * 2;
        const float* q1 = q0 + 8 * AT_PAD;
#pragma unroll
        for (int k = 0; k < 8; k++) {
            float2 f = *(const float2*)(q0 + k * 8);
            float2 g = *(const float2*)(q1 + k * 8);
            aq[k][0] = f.x; aq[k][1] = g.x; aq[k][2] = f.y; aq[k][3] = g.y;
        }
    }

    float O[8][4];
#pragma unroll
    for (int nt = 0; nt < 8; nt++)
#pragma unroll
        for (int j = 0; j < 4; j++) O[nt][j] = 0.0f;
    float m0v = -1e30f, m1v = -1e30f, l0v = 0.0f, l1v = 0.0f;

    const int tq0 = qbase + w * 16 + r;
    const int tq1 = tq0 + 8;
    const int ntiles = 2 * blockIdx.x + 2;
    float* pw = Ps + (w * 16) * AT_PAD;
    const int pos0 = (l4 < 2) ? l4 * 4 : (l4 - 2) * 4 + 1;

    for (int kt = 0; kt < ntiles; kt++) {
        const int kbase = kt * 64;
        __syncthreads();
#pragma unroll
        for (int i = 0; i < 4; i++) {
            int f = tid + i * 256;
            int t = f >> 4, dq = f & 15;
            float4 v = *(const float4*)(Kp + (size_t)(kbase + t) * HD + dq * 4);
            float* dst = Ksm + t * AT_PAD + (dq >> 1) * 8 + (dq & 1);
            dst[0] = v.x; dst[2] = v.y; dst[4] = v.z; dst[6] = v.w;
        }
#pragma unroll
        for (int i = 0; i < 4; i++) {
            int f = tid + i * 256;
            int d = f >> 4, t4 = f & 15;
            float4 v = *(const float4*)(Vtp + (size_t)d * TT + kbase + t4 * 4);
            float* dst = VTs + d * AT_PAD + (t4 >> 1) * 8 + (t4 & 1);
            dst[0] = v.x; dst[2] = v.y; dst[4] = v.z; dst[6] = v.w;
        }
        __syncthreads();

        float s[8][4];
#pragma unroll
        for (int nt = 0; nt < 8; nt++) {
#pragma unroll
            for (int j = 0; j < 4; j++) s[nt][j] = 0.0f;
            const float* kp = Ksm + (nt * 8 + r) * AT_PAD + l4 * 2;
#pragma unroll
            for (int k = 0; k < 8; k++) {
                float2 b = *(const float2*)(kp + k * 8);
                mma_tf32(s[nt], aq[k][0], aq[k][1], aq[k][2], aq[k][3], b.x, b.y);
            }
        }

        if (kbase + 63 <= qbase + w * 16) {
#pragma unroll
            for (int nt = 0; nt < 8; nt++)
#pragma unroll
                for (int j = 0; j < 4; j++) s[nt][j] *= scale;
        } else {
#pragma unroll
            for (int nt = 0; nt < 8; nt++) {
                int tk = kbase + nt * 8 + 2 * l4;
                s[nt][0] = (tk     <= tq0) ? s[nt][0] * scale : -1e30f;
                s[nt][1] = (tk + 1 <= tq0) ? s[nt][1] * scale : -1e30f;
                s[nt][2] = (tk     <= tq1) ? s[nt][2] * scale : -1e30f;
                s[nt][3] = (tk + 1 <= tq1) ? s[nt][3] * scale : -1e30f;
            }
        }

        float ml0 = -1e30f, ml1 = -1e30f;
#pragma unroll
        for (int nt = 0; nt < 8; nt++) {
            ml0 = fmaxf(ml0, fmaxf(s[nt][0], s[nt][1]));
            ml1 = fmaxf(ml1, fmaxf(s[nt][2], s[nt][3]));
        }
        ml0 = fmaxf(ml0, __shfl_xor_sync(0xffffffffu, ml0, 1));
        ml0 = fmaxf(ml0, __shfl_xor_sync(0xffffffffu, ml0, 2));
        ml1 = fmaxf(ml1, __shfl_xor_sync(0xffffffffu, ml1, 1));
        ml1 = fmaxf(ml1, __shfl_xor_sync(0xffffffffu, ml1, 2));
        float mn0 = fmaxf(m0v, ml0), mn1 = fmaxf(m1v, ml1);
        float c0 = __expf(m0v - mn0), c1 = __expf(m1v - mn1);
        float ps0 = 0.0f, ps1 = 0.0f;
#pragma unroll
        for (int nt = 0; nt < 8; nt++) {
            s[nt][0] = __expf(s[nt][0] - mn0); ps0 += s[nt][0];
            s[nt][1] = __expf(s[nt][1] - mn0); ps0 += s[nt][1];
            s[nt][2] = __expf(s[nt][2] - mn1); ps1 += s[nt][2];
            s[nt][3] = __expf(s[nt][3] - mn1); ps1 += s[nt][3];
        }
        ps0 += __shfl_xor_sync(0xffffffffu, ps0, 1);
        ps0 += __shfl_xor_sync(0xffffffffu, ps0, 2);
        ps1 += __shfl_xor_sync(0xffffffffu, ps1, 1);
        ps1 += __shfl_xor_sync(0xffffffffu, ps1, 2);
        l0v = l0v * c0 + ps0; m0v = mn0;
        l1v = l1v * c1 + ps1; m1v = mn1;
#pragma unroll
        for (int nt = 0; nt < 8; nt++) {
            O[nt][0] *= c0; O[nt][1] *= c0;
            O[nt][2] *= c1; O[nt][3] *= c1;
        }

#pragma unroll
        for (int nt = 0; nt < 8; nt++) {
            float* p0 = pw + r * AT_PAD + nt * 8 + pos0;
            float* p1 = pw + (r + 8) * AT_PAD + nt * 8 + pos0;
            p0[0] = to_tf32(s[nt][0]); p0[2] = to_tf32(s[nt][1]);
            p1[0] = to_tf32(s[nt][2]); p1[2] = to_tf32(s[nt][3]);
        }
        __syncwarp();

        float pa[8][4];
        {
            const float* p0 = pw + r * AT_PAD + l4 * 2;
            const float* p1 = p0 + 8 * AT_PAD;
#pragma unroll
            for (int k = 0; k < 8; k++) {
                float2 f = *(const float2*)(p0 + k * 8);
                float2 g = *(const float2*)(p1 + k * 8);
                pa[k][0] = f.x; pa[k][1] = g.x; pa[k][2] = f.y; pa[k][3] = g.y;
            }
        }

#pragma unroll
        for (int nt = 0; nt < 8; nt++) {
            const float* vp = VTs + (nt * 8 + r) * AT_PAD + l4 * 2;
#pragma unroll
            for (int k = 0; k < 8; k++) {
                float2 b = *(const float2*)(vp + k * 8);
                mma_tf32(O[nt], pa[k][0], pa[k][1], pa[k][2], pa[k][3], b.x, b.y);
            }
        }
    }

    const int b = bh >> 4;
    const int h = bh & 15;
    const int hb = h * 64;
    const float inv0 = 1.0f / l0v, inv1 = 1.0f / l1v;
    float* y0 = Yg + (size_t)(b * TT + tq0) * CC;
    float* y1 = Yg + (size_t)(b * TT + tq1) * CC;
#pragma unroll
    for (int nt = 0; nt < 8; nt++) {
        int c = hb + nt * 8 + 2 * l4;
        int base = c & ~31;
        int k5 = c & 31, k51 = (c + 1) & 31;
        int p0 = (k5 & 3) * 8 + (k5 >> 2);
        int p1 = (k51 & 3) * 8 + (k51 >> 2);
        y0[base + p0] = to_tf32(O[nt][0] * inv0);
        y0[base + p1] = to_tf32(O[nt][1] * inv0);
        y1[base + p0] = to_tf32(O[nt][2] * inv1);
        y1[base + p1] = to_tf32(O[nt][3] * inv1);
    }
}

// ---------------------------------------------------------------------------
// Launch
// ---------------------------------------------------------------------------
extern "C" void kernel_launch(void* const* d_in, const int* in_sizes, int n_in,
                              void* d_out, int out_size)
{
    const float* x     = (const float*)d_in[0];
    const float* Wqkv  = (const float*)d_in[1];
    const float* bqkv  = (const float*)d_in[2];
    const float* Wproj = (const float*)d_in[3];
    const float* bproj = (const float*)d_in[4];
    float* out = (float*)d_out;
    (void)in_sizes; (void)n_in; (void)out_size;

    float *yp, *xp, *wtq, *wtp;
    cudaGetSymbolAddress((void**)&yp,  g_y);
    cudaGetSymbolAddress((void**)&xp,  g_xp);
    cudaGetSymbolAddress((void**)&wtq, g_wtq);
    cudaGetSymbolAddress((void**)&wtp, g_wtp);

    cudaFuncSetAttribute(mma_gemm<0>, cudaFuncAttributeMaxDynamicSharedMemorySize, GEMM_SMEM);
    cudaFuncSetAttribute(mma_gemm<1>, cudaFuncAttributeMaxDynamicSharedMemorySize, GEMM_SMEM);
    cudaFuncSetAttribute(attn_mma,    cudaFuncAttributeMaxDynamicSharedMemorySize, AT_SMEM);

    {
        int total4 = MROWS * CC / 4;
        prep_A<<<(total4 + 255) / 256, 256>>>(x, xp, total4, CC);
        transpose_perm<<<dim3(N_QKV / 32, CC / 32), dim3(32, 8)>>>(Wqkv, wtq, CC, N_QKV);
        transpose_perm<<<dim3(CC / 32, CC / 32), dim3(32, 8)>>>(Wproj, wtp, CC, CC);
    }

    mma_gemm<0><<<dim3(N_QKV / 128, MROWS / 128), 256, GEMM_SMEM>>>(xp, wtq, bqkv, nullptr, N_QKV);
    attn_mma<<<dim3(TT / 128, BB * HH), 256, AT_SMEM>>>(yp);
    mma_gemm<1><<<dim3(CC / 128, MROWS / 128), 256, GEMM_SMEM>>>(yp, wtp, bproj, out, CC);
}